// round 1
// baseline (speedup 1.0000x reference)
#include <cuda_runtime.h>

#define NN 100000
#define EE 1600000
#define PP 100000
#define D  128
#define D4 32

// ---------------- scratch (device globals; no allocation) ----------------
__device__ __align__(128) float g_h  [(size_t)NN * D];
__device__ __align__(128) float g_hs [(size_t)NN * D];
__device__ __align__(128) float g_rep[(size_t)NN * D];
__device__ __align__(128) float g_e1 [(size_t)2 * PP * D];
__device__ __align__(128) float g_e2 [(size_t)2 * PP * D];
__device__ int   g_cnt_in [NN];
__device__ int   g_cnt_out[NN];
__device__ float g_rs_in  [NN];
__device__ float g_rs_out [NN];
__device__ int   g_row_ptr[NN + 1];
__device__ int   g_cursor [NN];
__device__ int   g_col    [EE];

// ---------------- graph structure kernels ----------------
__global__ void zero_cnt_kernel() {
    int v = blockIdx.x * blockDim.x + threadIdx.x;
    if (v < NN) { g_cnt_in[v] = 0; g_cnt_out[v] = 0; }
}

__global__ void count_deg_kernel(const int* __restrict__ src, const int* __restrict__ dst) {
    int e = blockIdx.x * blockDim.x + threadIdx.x;
    if (e < EE) {
        atomicAdd(&g_cnt_out[src[e]], 1);
        atomicAdd(&g_cnt_in [dst[e]], 1);
    }
}

// single-block scan over NN counts -> exclusive row_ptr
__global__ void scan_kernel() {
    __shared__ int sh[1024];
    __shared__ int carry;
    if (threadIdx.x == 0) carry = 0;
    __syncthreads();
    for (int base = 0; base < NN; base += 1024) {
        int i = base + threadIdx.x;
        int v = (i < NN) ? g_cnt_in[i] : 0;
        sh[threadIdx.x] = v;
        __syncthreads();
        for (int off = 1; off < 1024; off <<= 1) {
            int t = (threadIdx.x >= off) ? sh[threadIdx.x - off] : 0;
            __syncthreads();
            sh[threadIdx.x] += t;
            __syncthreads();
        }
        if (i < NN) g_row_ptr[i + 1] = carry + sh[threadIdx.x];
        __syncthreads();
        if (threadIdx.x == 0) carry += sh[1023];
        __syncthreads();
    }
    if (threadIdx.x == 0) g_row_ptr[0] = 0;
}

__global__ void rs_cursor_kernel() {
    int v = blockIdx.x * blockDim.x + threadIdx.x;
    if (v < NN) {
        int co = g_cnt_out[v]; if (co < 1) co = 1;
        int ci = g_cnt_in [v]; if (ci < 1) ci = 1;
        g_rs_out[v] = rsqrtf((float)co);
        g_rs_in [v] = rsqrtf((float)ci);
        g_cursor[v] = g_row_ptr[v];
    }
}

__global__ void scatter_edges_kernel(const int* __restrict__ src, const int* __restrict__ dst) {
    int e = blockIdx.x * blockDim.x + threadIdx.x;
    if (e < EE) {
        int pos = atomicAdd(&g_cursor[dst[e]], 1);
        g_col[pos] = src[e];
    }
}

// ---------------- GEMM: C[M,128] = act(A[M,128] @ W[128,128] + b) ----------------
// BM=64, BN=128 (full), BK=16, 256 threads, 8x4 outputs/thread.
template <int RELU, int REP>
__global__ void gemm_kernel(const float* __restrict__ A, const float* __restrict__ W,
                            const float* __restrict__ bias, float* __restrict__ C,
                            int M, float* __restrict__ rep, const float* __restrict__ gamma) {
    __shared__ float As[16][64];
    __shared__ float Ws[16][128];

    const int tid = threadIdx.x;
    const int tx  = tid & 31;   // col group: cols tx*4..tx*4+3
    const int ty  = tid >> 5;   // row group: rows ty*8..ty*8+7
    const int blockRow = blockIdx.x * 64;

    float acc[8][4];
#pragma unroll
    for (int i = 0; i < 8; i++)
#pragma unroll
        for (int j = 0; j < 4; j++) acc[i][j] = 0.0f;

    const int a_row = tid >> 2;  // 0..63
    const int a_c4  = tid & 3;   // 0..3
    const int gm    = blockRow + a_row;
    const bool a_ok = (gm < M);

    for (int kk = 0; kk < D; kk += 16) {
        float4 av = make_float4(0.f, 0.f, 0.f, 0.f);
        if (a_ok) av = *(const float4*)(A + (size_t)gm * D + kk + a_c4 * 4);
        As[a_c4 * 4 + 0][a_row] = av.x;
        As[a_c4 * 4 + 1][a_row] = av.y;
        As[a_c4 * 4 + 2][a_row] = av.z;
        As[a_c4 * 4 + 3][a_row] = av.w;
#pragma unroll
        for (int i = 0; i < 2; i++) {
            int idx = tid + i * 256;         // 0..511 float4s
            int wr  = idx >> 5;              // 0..15
            int wc4 = idx & 31;              // 0..31
            *(float4*)&Ws[wr][wc4 * 4] = *(const float4*)(W + (size_t)(kk + wr) * D + wc4 * 4);
        }
        __syncthreads();
#pragma unroll
        for (int k = 0; k < 16; k++) {
            float4 w4 = *(float4*)&Ws[k][tx * 4];
            float4 aa = *(float4*)&As[k][ty * 8];
            float4 ab = *(float4*)&As[k][ty * 8 + 4];
            float a0[8] = {aa.x, aa.y, aa.z, aa.w, ab.x, ab.y, ab.z, ab.w};
#pragma unroll
            for (int i = 0; i < 8; i++) {
                acc[i][0] += a0[i] * w4.x;
                acc[i][1] += a0[i] * w4.y;
                acc[i][2] += a0[i] * w4.z;
                acc[i][3] += a0[i] * w4.w;
            }
        }
        __syncthreads();
    }

    float4 b4 = *(const float4*)(bias + tx * 4);
    float g0 = 0.0f;
    if (REP) g0 = gamma[0];
#pragma unroll
    for (int i = 0; i < 8; i++) {
        int m = blockRow + ty * 8 + i;
        if (m < M) {
            float4 o;
            o.x = acc[i][0] + b4.x;
            o.y = acc[i][1] + b4.y;
            o.z = acc[i][2] + b4.z;
            o.w = acc[i][3] + b4.w;
            if (RELU) {
                o.x = fmaxf(o.x, 0.f); o.y = fmaxf(o.y, 0.f);
                o.z = fmaxf(o.z, 0.f); o.w = fmaxf(o.w, 0.f);
            }
            *(float4*)(C + (size_t)m * D + tx * 4) = o;
            if (REP) {
                float4 r;
                r.x = g0 * o.x; r.y = g0 * o.y; r.z = g0 * o.z; r.w = g0 * o.w;
                *(float4*)(rep + (size_t)m * D + tx * 4) = r;
            }
        }
    }
}

// ---------------- graph conv kernels ----------------
__global__ void prescale_kernel() {  // hs = h * rs_out[row]
    int idx = blockIdx.x * blockDim.x + threadIdx.x;  // over NN*32 float4s
    if (idx < NN * D4) {
        int row = idx >> 5;
        float  s = g_rs_out[row];
        float4 v = *(float4*)&g_h[(size_t)idx * 4];
        v.x *= s; v.y *= s; v.z *= s; v.w *= s;
        *(float4*)&g_hs[(size_t)idx * 4] = v;
    }
}

// warp per dst node: h[v] = rs_in[v] * sum_{e in row} hs[col[e]]; rep[v] += gamma[l+1]*h[v]
__global__ void aggregate_kernel(const float* __restrict__ gamma, int l) {
    int w    = (blockIdx.x * blockDim.x + threadIdx.x) >> 5;
    int lane = threadIdx.x & 31;
    if (w >= NN) return;
    int beg = g_row_ptr[w];
    int end = g_row_ptr[w + 1];
    float4 acc = make_float4(0.f, 0.f, 0.f, 0.f);
    int e = beg;
    int s_next = (e < end) ? g_col[e] : 0;
    while (e < end) {
        int s = s_next;
        ++e;
        if (e < end) s_next = g_col[e];
        float4 v = *(const float4*)&g_hs[(size_t)s * D + lane * 4];
        acc.x += v.x; acc.y += v.y; acc.z += v.z; acc.w += v.w;
    }
    float r  = g_rs_in[w];
    float gl = gamma[l + 1];
    float4 hn;
    hn.x = acc.x * r; hn.y = acc.y * r; hn.z = acc.z * r; hn.w = acc.w * r;
    size_t off = (size_t)w * D + lane * 4;
    *(float4*)&g_h[off] = hn;
    float4 rp = *(float4*)&g_rep[off];
    rp.x += gl * hn.x; rp.y += gl * hn.y; rp.z += gl * hn.z; rp.w += gl * hn.w;
    *(float4*)&g_rep[off] = rp;
}

// ---------------- predictor kernels ----------------
__global__ void edge_feat_kernel(const int* __restrict__ ps, const int* __restrict__ pd,
                                 const int* __restrict__ ns, const int* __restrict__ nd) {
    int w    = (blockIdx.x * blockDim.x + threadIdx.x) >> 5;  // 0..2P-1
    int lane = threadIdx.x & 31;
    if (w >= 2 * PP) return;
    int s, d;
    if (w < PP) { s = ps[w]; d = pd[w]; }
    else        { s = ns[w - PP]; d = nd[w - PP]; }
    float4 a = *(const float4*)&g_rep[(size_t)s * D + lane * 4];
    float4 b = *(const float4*)&g_rep[(size_t)d * D + lane * 4];
    float4 o;
    o.x = a.x * b.x; o.y = a.y * b.y; o.z = a.z * b.z; o.w = a.w * b.w;
    *(float4*)&g_e1[(size_t)w * D + lane * 4] = o;
}

__global__ void gemv_out_kernel(const float* __restrict__ Ein, const float* __restrict__ w3,
                                const float* __restrict__ b3, float* __restrict__ out) {
    int r    = (blockIdx.x * blockDim.x + threadIdx.x) >> 5;
    int lane = threadIdx.x & 31;
    if (r >= 2 * PP) return;
    float4 e  = *(const float4*)&Ein[(size_t)r * D + lane * 4];
    float4 ww = *(const float4*)&w3[lane * 4];
    float s = e.x * ww.x + e.y * ww.y + e.z * ww.z + e.w * ww.w;
#pragma unroll
    for (int off = 16; off > 0; off >>= 1) s += __shfl_xor_sync(0xFFFFFFFFu, s, off);
    if (lane == 0) out[r] = s + b3[0];
}

// ---------------- launch ----------------
extern "C" void kernel_launch(void* const* d_in, const int* in_sizes, int n_in,
                              void* d_out, int out_size) {
    const float* x   = (const float*)d_in[0];
    const float* w1  = (const float*)d_in[1];
    const float* b1  = (const float*)d_in[2];
    const float* w2  = (const float*)d_in[3];
    const float* b2  = (const float*)d_in[4];
    const float* gam = (const float*)d_in[5];
    const float* pw1 = (const float*)d_in[6];
    const float* pb1 = (const float*)d_in[7];
    const float* pw2 = (const float*)d_in[8];
    const float* pb2 = (const float*)d_in[9];
    const float* pw3 = (const float*)d_in[10];
    const float* pb3 = (const float*)d_in[11];
    const int* src = (const int*)d_in[12];
    const int* dst = (const int*)d_in[13];
    const int* ps  = (const int*)d_in[14];
    const int* pd  = (const int*)d_in[15];
    const int* ns  = (const int*)d_in[16];
    const int* nd  = (const int*)d_in[17];
    float* out = (float*)d_out;

    void *vh, *vhs, *vrep, *ve1, *ve2;
    cudaGetSymbolAddress(&vh,   g_h);
    cudaGetSymbolAddress(&vhs,  g_hs);
    cudaGetSymbolAddress(&vrep, g_rep);
    cudaGetSymbolAddress(&ve1,  g_e1);
    cudaGetSymbolAddress(&ve2,  g_e2);
    float* h   = (float*)vh;
    float* hs  = (float*)vhs;
    float* rep = (float*)vrep;
    float* e1  = (float*)ve1;
    float* e2  = (float*)ve2;

    const int TB = 256;
    // --- graph structure (CSR by dst) ---
    zero_cnt_kernel<<<(NN + TB - 1) / TB, TB>>>();
    count_deg_kernel<<<(EE + TB - 1) / TB, TB>>>(src, dst);
    scan_kernel<<<1, 1024>>>();
    rs_cursor_kernel<<<(NN + TB - 1) / TB, TB>>>();
    scatter_edges_kernel<<<(EE + TB - 1) / TB, TB>>>(src, dst);

    // --- node MLP: h = relu(x@W1+b1)@W2+b2 ; rep = gamma0*h ---
    gemm_kernel<1, 0><<<(NN + 63) / 64, TB>>>(x, w1, b1, hs, NN, nullptr, nullptr);
    gemm_kernel<0, 1><<<(NN + 63) / 64, TB>>>(hs, w2, b2, h, NN, rep, gam);

    // --- 3x GPR graph conv ---
    for (int l = 0; l < 3; l++) {
        prescale_kernel<<<(NN * D4 + TB - 1) / TB, TB>>>();
        aggregate_kernel<<<(NN * 32 + TB - 1) / TB, TB>>>(gam, l);
    }

    // --- predictor on pos||neg (2P rows) ---
    edge_feat_kernel<<<(2 * PP * 32 + TB - 1) / TB, TB>>>(ps, pd, ns, nd);
    gemm_kernel<1, 0><<<(2 * PP + 63) / 64, TB>>>(e1, pw1, pb1, e2, 2 * PP, nullptr, nullptr);
    gemm_kernel<1, 0><<<(2 * PP + 63) / 64, TB>>>(e2, pw2, pb2, e1, 2 * PP, nullptr, nullptr);
    gemv_out_kernel<<<(2 * PP * 32 + TB - 1) / TB, TB>>>(e1, pw3, pb3, out);
}

// round 2
// speedup vs baseline: 1.3174x; 1.3174x over previous
#include <cuda_runtime.h>

#define NN 100000
#define EE 1600000
#define PP 100000
#define D  128
#define NB 391   // ceil(NN/256)

// ---------------- scratch (device globals; no allocation) ----------------
__device__ __align__(128) float g_hA [(size_t)NN * D];  // pre-scaled features (ping)
__device__ __align__(128) float g_hB [(size_t)NN * D];  // pre-scaled features (pong)
__device__ __align__(128) float g_rep[(size_t)NN * D];
__device__ int   g_cnt_in [NN];
__device__ int   g_cnt_out[NN];
__device__ float g_rs_in  [NN];
__device__ float g_rs_out [NN];
__device__ int   g_row_ptr[NN + 1];
__device__ int   g_cursor [NN];
__device__ int   g_col    [EE];
__device__ int   g_bsum   [NB];
__device__ int   g_boff   [NB];

// ---------------- graph structure ----------------
__global__ void zero_cnt_kernel() {
    int v = blockIdx.x * blockDim.x + threadIdx.x;
    if (v < NN) { g_cnt_in[v] = 0; g_cnt_out[v] = 0; }
}

__global__ void count_deg_kernel(const int* __restrict__ src, const int* __restrict__ dst) {
    int e = blockIdx.x * blockDim.x + threadIdx.x;
    if (e < EE) {
        atomicAdd(&g_cnt_out[src[e]], 1);
        atomicAdd(&g_cnt_in [dst[e]], 1);
    }
}

// per-block reduce of cnt_in -> g_bsum
__global__ void scanA_kernel() {
    __shared__ int sh[256];
    int i = blockIdx.x * 256 + threadIdx.x;
    int v = (i < NN) ? g_cnt_in[i] : 0;
    sh[threadIdx.x] = v;
    __syncthreads();
    for (int off = 128; off > 0; off >>= 1) {
        if (threadIdx.x < off) sh[threadIdx.x] += sh[threadIdx.x + off];
        __syncthreads();
    }
    if (threadIdx.x == 0) g_bsum[blockIdx.x] = sh[0];
}

// single-block scan of NB block sums -> exclusive g_boff
__global__ void scanB_kernel() {
    __shared__ int sh[512];
    int t = threadIdx.x;
    int v = (t < NB) ? g_bsum[t] : 0;
    sh[t] = v;
    __syncthreads();
    for (int off = 1; off < 512; off <<= 1) {
        int x = (t >= off) ? sh[t - off] : 0;
        __syncthreads();
        sh[t] += x;
        __syncthreads();
    }
    if (t < NB) g_boff[t] = sh[t] - v;   // exclusive prefix
}

// block-local scan + offsets -> row_ptr, cursor, rs_in, rs_out
__global__ void scanC_kernel() {
    __shared__ int sh[256];
    int b = blockIdx.x;
    int i = b * 256 + threadIdx.x;
    int v = (i < NN) ? g_cnt_in[i] : 0;
    sh[threadIdx.x] = v;
    __syncthreads();
    for (int off = 1; off < 256; off <<= 1) {
        int x = (threadIdx.x >= off) ? sh[threadIdx.x - off] : 0;
        __syncthreads();
        sh[threadIdx.x] += x;
        __syncthreads();
    }
    if (i < NN) {
        int incl = g_boff[b] + sh[threadIdx.x];
        g_row_ptr[i + 1] = incl;
        g_cursor[i] = incl - v;
        int ci = v; if (ci < 1) ci = 1;
        int co = g_cnt_out[i]; if (co < 1) co = 1;
        g_rs_in [i] = rsqrtf((float)ci);
        g_rs_out[i] = rsqrtf((float)co);
        if (i == 0) g_row_ptr[0] = 0;
    }
}

__global__ void scatter_edges_kernel(const int* __restrict__ src, const int* __restrict__ dst) {
    int e = blockIdx.x * blockDim.x + threadIdx.x;
    if (e < EE) {
        int pos = atomicAdd(&g_cursor[dst[e]], 1);
        g_col[pos] = src[e];
    }
}

// ---------------- fused node MLP: hs = (relu(x@W1+b1)@W2+b2)*rs_out ; rep = gamma0*h ----
// BM=64, BN=128(full), 256 threads, 8x4 per thread.
__global__ void mlp_kernel(const float* __restrict__ x,
                           const float* __restrict__ w1, const float* __restrict__ b1,
                           const float* __restrict__ w2, const float* __restrict__ b2,
                           const float* __restrict__ gam,
                           float* __restrict__ hs, float* __restrict__ rep) {
    __shared__ float As[16][64];
    __shared__ float Ws[16][128];
    __shared__ float Ts[64 * 128];

    const int tid = threadIdx.x;
    const int tx  = tid & 31;
    const int ty  = tid >> 5;
    const int blockRow = blockIdx.x * 64;

    float acc[8][4];
#pragma unroll
    for (int i = 0; i < 8; i++)
#pragma unroll
        for (int j = 0; j < 4; j++) acc[i][j] = 0.0f;

    const int a_row = tid >> 2;
    const int a_c4  = tid & 3;
    const int gm    = blockRow + a_row;
    const bool a_ok = (gm < NN);

    // ---- GEMM1: relu(x@W1 + b1) -> Ts ----
    for (int kk = 0; kk < D; kk += 16) {
        float4 av = make_float4(0.f, 0.f, 0.f, 0.f);
        if (a_ok) av = *(const float4*)(x + (size_t)gm * D + kk + a_c4 * 4);
        As[a_c4 * 4 + 0][a_row] = av.x;
        As[a_c4 * 4 + 1][a_row] = av.y;
        As[a_c4 * 4 + 2][a_row] = av.z;
        As[a_c4 * 4 + 3][a_row] = av.w;
#pragma unroll
        for (int i = 0; i < 2; i++) {
            int idx = tid + i * 256;
            int wr  = idx >> 5;
            int wc4 = idx & 31;
            *(float4*)&Ws[wr][wc4 * 4] = *(const float4*)(w1 + (size_t)(kk + wr) * D + wc4 * 4);
        }
        __syncthreads();
#pragma unroll
        for (int k = 0; k < 16; k++) {
            float4 w4 = *(float4*)&Ws[k][tx * 4];
            float4 aa = *(float4*)&As[k][ty * 8];
            float4 ab = *(float4*)&As[k][ty * 8 + 4];
            float a0[8] = {aa.x, aa.y, aa.z, aa.w, ab.x, ab.y, ab.z, ab.w};
#pragma unroll
            for (int i = 0; i < 8; i++) {
                acc[i][0] += a0[i] * w4.x;
                acc[i][1] += a0[i] * w4.y;
                acc[i][2] += a0[i] * w4.z;
                acc[i][3] += a0[i] * w4.w;
            }
        }
        __syncthreads();
    }
    {
        float4 b4 = *(const float4*)(b1 + tx * 4);
#pragma unroll
        for (int i = 0; i < 8; i++) {
            float4 o;
            o.x = fmaxf(acc[i][0] + b4.x, 0.f);
            o.y = fmaxf(acc[i][1] + b4.y, 0.f);
            o.z = fmaxf(acc[i][2] + b4.z, 0.f);
            o.w = fmaxf(acc[i][3] + b4.w, 0.f);
            *(float4*)&Ts[(ty * 8 + i) * 128 + tx * 4] = o;
        }
    }
    __syncthreads();

    // ---- GEMM2: Ts @ W2 + b2 ----
#pragma unroll
    for (int i = 0; i < 8; i++)
#pragma unroll
        for (int j = 0; j < 4; j++) acc[i][j] = 0.0f;

    for (int kk = 0; kk < D; kk += 16) {
#pragma unroll
        for (int i = 0; i < 2; i++) {
            int idx = tid + i * 256;
            int wr  = idx >> 5;
            int wc4 = idx & 31;
            *(float4*)&Ws[wr][wc4 * 4] = *(const float4*)(w2 + (size_t)(kk + wr) * D + wc4 * 4);
        }
        __syncthreads();
#pragma unroll
        for (int k = 0; k < 16; k++) {
            float4 w4 = *(float4*)&Ws[k][tx * 4];
#pragma unroll
            for (int i = 0; i < 8; i++) {
                float a0 = Ts[(ty * 8 + i) * 128 + kk + k];
                acc[i][0] += a0 * w4.x;
                acc[i][1] += a0 * w4.y;
                acc[i][2] += a0 * w4.z;
                acc[i][3] += a0 * w4.w;
            }
        }
        __syncthreads();
    }

    float4 b4 = *(const float4*)(b2 + tx * 4);
    float g0 = gam[0];
#pragma unroll
    for (int i = 0; i < 8; i++) {
        int m = blockRow + ty * 8 + i;
        if (m < NN) {
            float so = g_rs_out[m];
            float4 h;
            h.x = acc[i][0] + b4.x;
            h.y = acc[i][1] + b4.y;
            h.z = acc[i][2] + b4.z;
            h.w = acc[i][3] + b4.w;
            float4 r;
            r.x = g0 * h.x; r.y = g0 * h.y; r.z = g0 * h.z; r.w = g0 * h.w;
            *(float4*)(rep + (size_t)m * D + tx * 4) = r;
            float4 s;
            s.x = so * h.x; s.y = so * h.y; s.z = so * h.z; s.w = so * h.w;
            *(float4*)(hs + (size_t)m * D + tx * 4) = s;
        }
    }
}

// ---------------- graph conv: warp per dst node ----------------
// sum = Σ hin[col[e]]; rep += gamma[l+1]*rs_in*sum; hout = rs_in*rs_out*sum (unless last)
__global__ void aggregate_kernel(const float* __restrict__ hin, float* __restrict__ hout,
                                 const float* __restrict__ gamma, int l, int last) {
    int w    = (blockIdx.x * blockDim.x + threadIdx.x) >> 5;
    int lane = threadIdx.x & 31;
    if (w >= NN) return;
    int beg = g_row_ptr[w];
    int end = g_row_ptr[w + 1];
    float4 acc = make_float4(0.f, 0.f, 0.f, 0.f);
    for (int e = beg; e < end; e++) {
        int s = g_col[e];
        float4 v = *(const float4*)&hin[(size_t)s * D + lane * 4];
        acc.x += v.x; acc.y += v.y; acc.z += v.z; acc.w += v.w;
    }
    float rin = g_rs_in[w];
    float gl  = gamma[l + 1] * rin;
    size_t off = (size_t)w * D + lane * 4;
    float4 rp = *(float4*)&g_rep[off];
    rp.x += gl * acc.x; rp.y += gl * acc.y; rp.z += gl * acc.z; rp.w += gl * acc.w;
    *(float4*)&g_rep[off] = rp;
    if (!last) {
        float s2 = rin * g_rs_out[w];
        float4 hn;
        hn.x = s2 * acc.x; hn.y = s2 * acc.y; hn.z = s2 * acc.z; hn.w = s2 * acc.w;
        *(float4*)&hout[off] = hn;
    }
}

// ---------------- fused predictor: out = relu(relu((rep[s]*rep[d])@W1+b1)@W2+b2)@w3+b3 ----
// BM=64 edges, 256 threads, 8x4 per thread, in-place smem chaining.
__global__ void pred_kernel(const int* __restrict__ ps, const int* __restrict__ pd,
                            const int* __restrict__ ns, const int* __restrict__ nd,
                            const float* __restrict__ w1, const float* __restrict__ b1,
                            const float* __restrict__ w2, const float* __restrict__ b2,
                            const float* __restrict__ w3, const float* __restrict__ b3,
                            const float* __restrict__ rep, float* __restrict__ out) {
    __shared__ float E[64 * 128];
    __shared__ float Ws[16][128];
    __shared__ float w3s[128];
    __shared__ int   sidx[64], didx[64];

    const int tid = threadIdx.x;
    const int tx  = tid & 31;
    const int ty  = tid >> 5;
    const int base = blockIdx.x * 64;

    if (tid < 64) {
        int w = base + tid;
        int s, d;
        if (w < PP) { s = ps[w]; d = pd[w]; }
        else        { s = ns[w - PP]; d = nd[w - PP]; }
        sidx[tid] = s; didx[tid] = d;
    }
    if (tid < 128) w3s[tid] = w3[tid];
    __syncthreads();

    // gather + elementwise multiply -> E
#pragma unroll
    for (int it = 0; it < 8; it++) {
        int c  = tid + it * 256;      // 0..2047 float4 chunks
        int r  = c >> 5;
        int c4 = c & 31;
        float4 a = *(const float4*)(rep + (size_t)sidx[r] * D + c4 * 4);
        float4 b = *(const float4*)(rep + (size_t)didx[r] * D + c4 * 4);
        float4 o;
        o.x = a.x * b.x; o.y = a.y * b.y; o.z = a.z * b.z; o.w = a.w * b.w;
        *(float4*)&E[r * 128 + c4 * 4] = o;
    }
    __syncthreads();

    float acc[8][4];

    // ---- layer 1 ----
#pragma unroll
    for (int i = 0; i < 8; i++)
#pragma unroll
        for (int j = 0; j < 4; j++) acc[i][j] = 0.0f;
    for (int kk = 0; kk < D; kk += 16) {
#pragma unroll
        for (int i = 0; i < 2; i++) {
            int idx = tid + i * 256;
            int wr  = idx >> 5;
            int wc4 = idx & 31;
            *(float4*)&Ws[wr][wc4 * 4] = *(const float4*)(w1 + (size_t)(kk + wr) * D + wc4 * 4);
        }
        __syncthreads();
#pragma unroll
        for (int k = 0; k < 16; k++) {
            float4 w4 = *(float4*)&Ws[k][tx * 4];
#pragma unroll
            for (int i = 0; i < 8; i++) {
                float a0 = E[(ty * 8 + i) * 128 + kk + k];
                acc[i][0] += a0 * w4.x;
                acc[i][1] += a0 * w4.y;
                acc[i][2] += a0 * w4.z;
                acc[i][3] += a0 * w4.w;
            }
        }
        __syncthreads();
    }
    {
        float4 b4 = *(const float4*)(b1 + tx * 4);
#pragma unroll
        for (int i = 0; i < 8; i++) {
            float4 o;
            o.x = fmaxf(acc[i][0] + b4.x, 0.f);
            o.y = fmaxf(acc[i][1] + b4.y, 0.f);
            o.z = fmaxf(acc[i][2] + b4.z, 0.f);
            o.w = fmaxf(acc[i][3] + b4.w, 0.f);
            *(float4*)&E[(ty * 8 + i) * 128 + tx * 4] = o;
        }
    }
    __syncthreads();

    // ---- layer 2 ----
#pragma unroll
    for (int i = 0; i < 8; i++)
#pragma unroll
        for (int j = 0; j < 4; j++) acc[i][j] = 0.0f;
    for (int kk = 0; kk < D; kk += 16) {
#pragma unroll
        for (int i = 0; i < 2; i++) {
            int idx = tid + i * 256;
            int wr  = idx >> 5;
            int wc4 = idx & 31;
            *(float4*)&Ws[wr][wc4 * 4] = *(const float4*)(w2 + (size_t)(kk + wr) * D + wc4 * 4);
        }
        __syncthreads();
#pragma unroll
        for (int k = 0; k < 16; k++) {
            float4 w4 = *(float4*)&Ws[k][tx * 4];
#pragma unroll
            for (int i = 0; i < 8; i++) {
                float a0 = E[(ty * 8 + i) * 128 + kk + k];
                acc[i][0] += a0 * w4.x;
                acc[i][1] += a0 * w4.y;
                acc[i][2] += a0 * w4.z;
                acc[i][3] += a0 * w4.w;
            }
        }
        __syncthreads();
    }

    // ---- layer 3: relu, dot with w3, warp reduce ----
    {
        float4 b4 = *(const float4*)(b2 + tx * 4);
        float4 wv = *(float4*)&w3s[tx * 4];
        float bb3 = b3[0];
#pragma unroll
        for (int i = 0; i < 8; i++) {
            float r0 = fmaxf(acc[i][0] + b4.x, 0.f);
            float r1 = fmaxf(acc[i][1] + b4.y, 0.f);
            float r2 = fmaxf(acc[i][2] + b4.z, 0.f);
            float r3 = fmaxf(acc[i][3] + b4.w, 0.f);
            float p = r0 * wv.x + r1 * wv.y + r2 * wv.z + r3 * wv.w;
#pragma unroll
            for (int off = 16; off > 0; off >>= 1)
                p += __shfl_xor_sync(0xFFFFFFFFu, p, off);
            if (tx == 0) out[base + ty * 8 + i] = p + bb3;
        }
    }
}

// ---------------- launch ----------------
extern "C" void kernel_launch(void* const* d_in, const int* in_sizes, int n_in,
                              void* d_out, int out_size) {
    const float* x   = (const float*)d_in[0];
    const float* w1  = (const float*)d_in[1];
    const float* b1  = (const float*)d_in[2];
    const float* w2  = (const float*)d_in[3];
    const float* b2  = (const float*)d_in[4];
    const float* gam = (const float*)d_in[5];
    const float* pw1 = (const float*)d_in[6];
    const float* pb1 = (const float*)d_in[7];
    const float* pw2 = (const float*)d_in[8];
    const float* pb2 = (const float*)d_in[9];
    const float* pw3 = (const float*)d_in[10];
    const float* pb3 = (const float*)d_in[11];
    const int* src = (const int*)d_in[12];
    const int* dst = (const int*)d_in[13];
    const int* ps  = (const int*)d_in[14];
    const int* pd  = (const int*)d_in[15];
    const int* ns  = (const int*)d_in[16];
    const int* nd  = (const int*)d_in[17];
    float* out = (float*)d_out;

    void *vA, *vB, *vrep;
    cudaGetSymbolAddress(&vA,   g_hA);
    cudaGetSymbolAddress(&vB,   g_hB);
    cudaGetSymbolAddress(&vrep, g_rep);
    float* hA  = (float*)vA;
    float* hB  = (float*)vB;
    float* rep = (float*)vrep;

    const int TB = 256;
    // graph structure (CSR by dst)
    zero_cnt_kernel<<<NB, TB>>>();
    count_deg_kernel<<<(EE + TB - 1) / TB, TB>>>(src, dst);
    scanA_kernel<<<NB, TB>>>();
    scanB_kernel<<<1, 512>>>();
    scanC_kernel<<<NB, TB>>>();
    scatter_edges_kernel<<<(EE + TB - 1) / TB, TB>>>(src, dst);

    // fused node MLP -> hA (pre-scaled), rep = gamma0*h
    mlp_kernel<<<(NN + 63) / 64, TB>>>(x, w1, b1, w2, b2, gam, hA, rep);

    // 3x GPR graph conv (ping-pong, fused scaling)
    aggregate_kernel<<<(NN * 32 + TB - 1) / TB, TB>>>(hA, hB, gam, 0, 0);
    aggregate_kernel<<<(NN * 32 + TB - 1) / TB, TB>>>(hB, hA, gam, 1, 0);
    aggregate_kernel<<<(NN * 32 + TB - 1) / TB, TB>>>(hA, hB, gam, 2, 1);

    // fused predictor on pos||neg (2P rows)
    pred_kernel<<<(2 * PP) / 64, TB>>>(ps, pd, ns, nd, pw1, pb1, pw2, pb2, pw3, pb3, rep, out);
}